// round 3
// baseline (speedup 1.0000x reference)
#include <cuda_runtime.h>

// B=32, P=3, D=300, N=2048.  x,y: [B,P,D,N] fp32.
// out: [B, P*N, 3] = {cos, l2, l1} per (b,p,n) vector of length D (stride N).
//
// D-split x2: each thread reduces 150 d-rows of one column; lane pairs
// (lane ^ 16, same warp) cover the two halves and combine via shfl_xor.
// 393216 threads -> ~100% occupancy (prev: grid-limited 61%, DRAM 74%).

#define D_DIM 300
#define D_HALF 150
#define N_DIM 2048
#define BP 96
#define THREADS 256

__global__ __launch_bounds__(THREADS, 8)
void sim_measure_kernel(const float* __restrict__ x,
                        const float* __restrict__ y,
                        float* __restrict__ out)
{
    const int idx  = blockIdx.x * THREADS + threadIdx.x;
    const int lane = idx & 31;
    const int gwarp = idx >> 5;

    // global column id: 16 columns per warp
    const int c  = (gwarp << 4) | (lane & 15);    // 0 .. BP*N_DIM-1
    const int n  = c & (N_DIM - 1);
    const int bp = c >> 11;
    const int half = lane >> 4;                   // 0 or 1
    const int d0 = half * D_HALF;

    const float* __restrict__ xp =
        x + (size_t)bp * D_DIM * N_DIM + (size_t)d0 * N_DIM + n;
    const float* __restrict__ yp =
        y + (size_t)bp * D_DIM * N_DIM + (size_t)d0 * N_DIM + n;

    float dot = 0.f, xx = 0.f, yy = 0.f, dd = 0.f, l1 = 0.f;

    #pragma unroll 5
    for (int d = 0; d < D_HALF; ++d) {
        const float av = __ldg(xp + (size_t)d * N_DIM);
        const float bv = __ldg(yp + (size_t)d * N_DIM);
        dot = fmaf(av, bv, dot);
        xx  = fmaf(av, av, xx);
        yy  = fmaf(bv, bv, yy);
        const float df = av - bv;
        dd  = fmaf(df, df, dd);
        l1 += fabsf(df);
    }

    // combine the two D-halves (partner = lane ^ 16, same column)
    dot += __shfl_xor_sync(0xFFFFFFFFu, dot, 16);
    xx  += __shfl_xor_sync(0xFFFFFFFFu, xx,  16);
    yy  += __shfl_xor_sync(0xFFFFFFFFu, yy,  16);
    dd  += __shfl_xor_sync(0xFFFFFFFFu, dd,  16);
    l1  += __shfl_xor_sync(0xFFFFFFFFu, l1,  16);

    if (half == 0) {
        float* o = out + (size_t)c * 3;
        o[0] = dot * rsqrtf(xx * yy);
        o[1] = sqrtf(dd);
        o[2] = l1;
    }
}

extern "C" void kernel_launch(void* const* d_in, const int* in_sizes, int n_in,
                              void* d_out, int out_size)
{
    const float* x = (const float*)d_in[0];
    const float* y = (const float*)d_in[1];
    float* out = (float*)d_out;

    const int total_threads = BP * N_DIM * 2;    // 393216
    const int blocks = total_threads / THREADS;  // 1536
    sim_measure_kernel<<<blocks, THREADS>>>(x, y, out);
}

// round 4
// speedup vs baseline: 1.1612x; 1.1612x over previous
#include <cuda_runtime.h>

// B=32, P=3, D=300, N=2048.  x,y: [B,P,D,N] fp32.
// out: [B, P*N, 3] = {cos, l2, l1} per (b,p,n) vector of length D (stride N).
//
// D split across WARPS (3 chunks of 100), combined in smem. Every warp's LDG
// stays a single contiguous 128B line (32 consecutive columns) — the R3
// regression came from intra-warp address divergence (2x64B per LDG).
// Block = 384 thr = 4 column-warps x 3 d-chunks = 128 columns per block.
// Grid = 1536 -> ~1.95 full-occupancy waves (93.75% occ), no big tail.

#define D_DIM 300
#define D_CHUNK 100
#define N_DIM 2048
#define BP 96
#define THREADS 384
#define COLS_PER_BLOCK 128

__global__ __launch_bounds__(THREADS, 5)
void sim_measure_kernel(const float* __restrict__ x,
                        const float* __restrict__ y,
                        float* __restrict__ out)
{
    // partials from chunks 1 and 2: [2][128 cols][5 vals]
    __shared__ float part[2][COLS_PER_BLOCK][5];

    const int tid   = threadIdx.x;
    const int wid   = tid >> 5;          // 0..11
    const int lane  = tid & 31;
    const int chunk = wid >> 2;          // 0..2  (d-range)
    const int cw    = wid & 3;           // 0..3  (column warp)
    const int lcol  = (cw << 5) | lane;  // 0..127 within block

    const int c  = blockIdx.x * COLS_PER_BLOCK + lcol;   // global column
    const int n  = c & (N_DIM - 1);
    const int bp = c >> 11;
    const int d0 = chunk * D_CHUNK;

    const float* __restrict__ xp =
        x + (size_t)bp * D_DIM * N_DIM + (size_t)d0 * N_DIM + n;
    const float* __restrict__ yp =
        y + (size_t)bp * D_DIM * N_DIM + (size_t)d0 * N_DIM + n;

    float dot = 0.f, xx = 0.f, yy = 0.f, dd = 0.f, l1 = 0.f;

    #pragma unroll 5
    for (int d = 0; d < D_CHUNK; ++d) {
        const float av = __ldg(xp + (size_t)d * N_DIM);
        const float bv = __ldg(yp + (size_t)d * N_DIM);
        dot = fmaf(av, bv, dot);
        xx  = fmaf(av, av, xx);
        yy  = fmaf(bv, bv, yy);
        const float df = av - bv;
        dd  = fmaf(df, df, dd);
        l1 += fabsf(df);
    }

    if (chunk != 0) {
        float* p = part[chunk - 1][lcol];
        p[0] = dot; p[1] = xx; p[2] = yy; p[3] = dd; p[4] = l1;
    }
    __syncthreads();

    if (chunk == 0) {
        const float* p0 = part[0][lcol];
        const float* p1 = part[1][lcol];
        dot += p0[0] + p1[0];
        xx  += p0[1] + p1[1];
        yy  += p0[2] + p1[2];
        dd  += p0[3] + p1[3];
        l1  += p0[4] + p1[4];

        float* o = out + (size_t)c * 3;
        o[0] = dot * rsqrtf(xx * yy);
        o[1] = sqrtf(dd);
        o[2] = l1;
    }
}

extern "C" void kernel_launch(void* const* d_in, const int* in_sizes, int n_in,
                              void* d_out, int out_size)
{
    const float* x = (const float*)d_in[0];
    const float* y = (const float*)d_in[1];
    float* out = (float*)d_out;

    const int blocks = BP * N_DIM / COLS_PER_BLOCK;   // 1536
    sim_measure_kernel<<<blocks, THREADS>>>(x, y, out);
}

// round 5
// speedup vs baseline: 2.2895x; 1.9717x over previous
#include <cuda_runtime.h>

// B=32, P=3, D=300, N=2048.  x,y: [B,P,D,N] fp32.
// out: [B, P*N, 3] = {cos, l2, l1} per (b,p,n) vector of length D (stride N).
//
// R2 shape restored (one thread <-> one full-D column; D-splits regressed 2x
// in R3/R4). Fix R2's limiter: grid imbalance. 768x256 put 5-or-6 blocks/SM
// (16% tail); 3072x64 puts 20-or-21 blocks/SM (1.2% tail), all resident in
// one wave. Warp loads remain single contiguous 128B lines.

#define D_DIM 300
#define N_DIM 2048
#define BP 96
#define THREADS 64

__global__ __launch_bounds__(THREADS)
void sim_measure_kernel(const float* __restrict__ x,
                        const float* __restrict__ y,
                        float* __restrict__ out)
{
    const int idx = blockIdx.x * THREADS + threadIdx.x;   // 0 .. BP*N-1
    const int n  = idx & (N_DIM - 1);
    const int bp = idx >> 11;                             // / 2048

    const float* __restrict__ xp = x + (size_t)bp * D_DIM * N_DIM + n;
    const float* __restrict__ yp = y + (size_t)bp * D_DIM * N_DIM + n;

    float dot = 0.f, xx = 0.f, yy = 0.f, dd = 0.f, l1 = 0.f;

    #pragma unroll 5
    for (int d = 0; d < D_DIM; ++d) {
        const float av = __ldg(xp + (size_t)d * N_DIM);
        const float bv = __ldg(yp + (size_t)d * N_DIM);
        dot = fmaf(av, bv, dot);
        xx  = fmaf(av, av, xx);
        yy  = fmaf(bv, bv, yy);
        const float df = av - bv;
        dd  = fmaf(df, df, dd);
        l1 += fabsf(df);
    }

    // out layout: [bp, n, 3]
    float* o = out + ((size_t)bp * N_DIM + n) * 3;
    o[0] = dot * rsqrtf(xx * yy);
    o[1] = sqrtf(dd);
    o[2] = l1;
}

extern "C" void kernel_launch(void* const* d_in, const int* in_sizes, int n_in,
                              void* d_out, int out_size)
{
    const float* x = (const float*)d_in[0];
    const float* y = (const float*)d_in[1];
    float* out = (float*)d_out;

    const int total_threads = BP * N_DIM;        // 196608
    const int blocks = total_threads / THREADS;  // 3072
    sim_measure_kernel<<<blocks, THREADS>>>(x, y, out);
}